// round 15
// baseline (speedup 1.0000x reference)
#include <cuda_runtime.h>
#include <math.h>

#define B_   4096
#define D_   1024
#define F_   24576
#define K1   32      /* TOPK */
#define K2_  256     /* DEAD_TOPK */
#define DEAD_CUT 100000
#define NTH  512     /* threads in row kernel */

/* GEMM tile */
#define BM 256
#define BN 96
#define BK 16
#define GTH 384
#define ASTRIDE 260   /* padded As row (floats), 16B-aligned, 2-way store conflicts */
#define BSTRIDE 100   /* padded Bs row */

#define GRID_X (F_ / BN)     /* 256 */
#define GRID_Y (B_ / BM)     /* 16  */
#define NBLK   (GRID_X * GRID_Y)   /* 4096 */

// ---------------------------------------------------------------------------
// Scratch (device globals: no cudaMalloc allowed)
// ---------------------------------------------------------------------------
__device__ float  g_project[(size_t)B_ * (size_t)F_];   // 402 MB
__device__ float  g_embc[(size_t)B_ * (size_t)D_];      // 16 MB: embed - bias
__device__ double g_part[NBLK][2];                      // per-CTA (sum, sumsq)
__device__ double g_sum;
__device__ double g_sumsq;

// Pre-subtract bias once (bit-identical rounding to doing it in the loader).
__global__ __launch_bounds__(512)
void pre_kernel(const float* __restrict__ embed, const float* __restrict__ bias) {
    const int i = blockIdx.x * 512 + threadIdx.x;
    g_embc[i] = embed[i] - bias[i & (D_ - 1)];
}

// Deterministic reduction of per-CTA partials -> g_sum / g_sumsq.
__global__ __launch_bounds__(512)
void reduce_stats_kernel() {
    const int tid = threadIdx.x;
    double s = 0.0, ss = 0.0;
    for (int i = tid; i < NBLK; i += 512) {
        s  += g_part[i][0];
        ss += g_part[i][1];
    }
    __shared__ double sh_s[512], sh_ss[512];
    sh_s[tid] = s; sh_ss[tid] = ss;
    __syncthreads();
    for (int off = 256; off > 0; off >>= 1) {
        if (tid < off) {
            sh_s[tid]  += sh_s[tid + off];
            sh_ss[tid] += sh_ss[tid + off];
        }
        __syncthreads();
    }
    if (tid == 0) { g_sum = sh_s[0]; g_sumsq = sh_ss[0]; }
}

// ---------------------------------------------------------------------------
// packed f32x2 helpers (SASS FFMA2). Each half is an IEEE fp32 FMA.
// ---------------------------------------------------------------------------
__device__ __forceinline__ void fma2(unsigned long long& d,
                                     unsigned long long a,
                                     unsigned long long b) {
    asm("fma.rn.f32x2 %0, %1, %2, %0;" : "+l"(d) : "l"(a), "l"(b));
}
__device__ __forceinline__ void add2(unsigned long long& d,
                                     unsigned long long a) {
    asm("add.rn.f32x2 %0, %0, %1;" : "+l"(d) : "l"(a));
}
__device__ __forceinline__ unsigned long long dupf(float x) {
    unsigned long long r;
    asm("mov.b64 %0, {%1, %1};" : "=l"(r) : "f"(x));
    return r;
}
__device__ __forceinline__ void unpack2(unsigned long long v, float& lo, float& hi) {
    asm("mov.b64 {%0, %1}, %2;" : "=f"(lo), "=f"(hi) : "l"(v));
}

// XOR swizzle of 16B chunks within an As row: chunk q -> q ^ ((q>>3)&1).
// Verified conflict-free for 32-lane 32B-strided LDS.128 (all 4 phases, both
// even and odd chunk streams).
__device__ __forceinline__ int aswiz(int c) {
    int q = c >> 2;
    q ^= (q >> 3) & 1;
    return (q << 2) | (c & 3);
}

// ---------------------------------------------------------------------------
// SGEMM: project[b,f] = sum_d embc[b,d] * W[f,d]
// 256x96 tile, BK=16, 384 threads, 8x8 micro-tile, double buffered, FFMA2.
// warp = column-group (B loads are warp-broadcast, conflict-free);
// lane = row-group (A loads swizzled conflict-free).
// Per-element FP op sequence identical to R8..R14 -> bit-exact.
// ---------------------------------------------------------------------------
__global__ __launch_bounds__(GTH, 1)
void gemm_kernel(const float* __restrict__ W)
{
    __shared__ __align__(16) float As[2][BK][ASTRIDE];
    __shared__ __align__(16) float Bs[2][BK][BSTRIDE];

    const int tid  = threadIdx.x;
    const int lane = tid & 31;   // row-group: rows lane*8 .. lane*8+7
    const int w    = tid >> 5;   // col-group: cols w*8 .. w*8+7
    const int row0 = blockIdx.y * BM;
    const int col0 = blockIdx.x * BN;

    // ---- loader mapping ----
    // A slab: 256 rows x 16 k = 1024 float4; 384 threads -> 3 iters (3rd if tid<256)
    // B slab:  96 rows x 16 k =  384 float4; exactly 1 per thread
    const int ar0 = tid >> 2;          // 0..95
    const int aq  = tid & 3;           // float4 index within 16-wide k slab
    const int kc  = aq * 4;
    const int ap0 = aswiz(ar0);
    const int ap1 = aswiz(ar0 + 96);
    const int ap2 = aswiz((ar0 + 192) & 255);
    const bool has3 = (tid < 256);

    const float* Ap = g_embc + (size_t)(row0 + ar0) * D_ + aq * 4;
    const float* Bp = W      + (size_t)(col0 + ar0) * D_ + aq * 4;
    const size_t AR1 = (size_t)96  * D_;
    const size_t AR2 = (size_t)192 * D_;

    // paired accumulators: acc2[p][j] = rows (lane*8+2p, lane*8+2p+1), col w*8+j
    unsigned long long acc2[4][8];
#pragma unroll
    for (int p = 0; p < 4; p++)
#pragma unroll
        for (int j = 0; j < 8; j++) acc2[p][j] = 0ull;

    float4 a_pf0, a_pf1, a_pf2, b_pf;

    // preload slab 0
    a_pf0 = *(const float4*)(Ap);
    a_pf1 = *(const float4*)(Ap + AR1);
    if (has3) a_pf2 = *(const float4*)(Ap + AR2);
    b_pf  = *(const float4*)(Bp);

    int buf = 0;
    {
        As[0][kc+0][ap0] = a_pf0.x;  As[0][kc+1][ap0] = a_pf0.y;
        As[0][kc+2][ap0] = a_pf0.z;  As[0][kc+3][ap0] = a_pf0.w;
        As[0][kc+0][ap1] = a_pf1.x;  As[0][kc+1][ap1] = a_pf1.y;
        As[0][kc+2][ap1] = a_pf1.z;  As[0][kc+3][ap1] = a_pf1.w;
        if (has3) {
            As[0][kc+0][ap2] = a_pf2.x;  As[0][kc+1][ap2] = a_pf2.y;
            As[0][kc+2][ap2] = a_pf2.z;  As[0][kc+3][ap2] = a_pf2.w;
        }
        Bs[0][kc+0][ar0] = b_pf.x;  Bs[0][kc+1][ar0] = b_pf.y;
        Bs[0][kc+2][ar0] = b_pf.z;  Bs[0][kc+3][ar0] = b_pf.w;
    }
    __syncthreads();

    const int txs0 = aswiz(lane * 8);      // rows lane*8..+3
    const int txs1 = aswiz(lane * 8 + 4);  // rows lane*8+4..+7
    const int bcol = w * 8;
    const int NT = D_ / BK;                // 64

    for (int t = 0; t < NT; t++) {
        if (t + 1 < NT) {
            const int k0 = (t + 1) * BK;
            a_pf0 = *(const float4*)(Ap + k0);
            a_pf1 = *(const float4*)(Ap + AR1 + k0);
            if (has3) a_pf2 = *(const float4*)(Ap + AR2 + k0);
            b_pf  = *(const float4*)(Bp + k0);
        }
        // per-tile partial sums (fresh registers -> short rounding chains)
        unsigned long long ts2[4][8];
#pragma unroll
        for (int p = 0; p < 4; p++)
#pragma unroll
            for (int j = 0; j < 8; j++) ts2[p][j] = 0ull;

#pragma unroll
        for (int kk = 0; kk < BK; kk++) {
            // A: two swizzled LDS.128 -> 4 row-pairs
            ulonglong2 pa0 = *(const ulonglong2*)&As[buf][kk][txs0];
            ulonglong2 pa1 = *(const ulonglong2*)&As[buf][kk][txs1];
            unsigned long long a2[4] = { pa0.x, pa0.y, pa1.x, pa1.y };
            // B: two warp-broadcast LDS.128
            float4 f0 = *(const float4*)&Bs[buf][kk][bcol];
            float4 f1 = *(const float4*)&Bs[buf][kk][bcol + 4];
            float bv[8] = { f0.x, f0.y, f0.z, f0.w, f1.x, f1.y, f1.z, f1.w };
#pragma unroll
            for (int j = 0; j < 8; j++) {
                const unsigned long long b2 = dupf(bv[j]);   // short live range
#pragma unroll
                for (int p = 0; p < 4; p++)
                    fma2(ts2[p][j], a2[p], b2);
            }
        }
#pragma unroll
        for (int p = 0; p < 4; p++)
#pragma unroll
            for (int j = 0; j < 8; j++)
                add2(acc2[p][j], ts2[p][j]);

        if (t + 1 < NT) {
            const int nb = buf ^ 1;
            As[nb][kc+0][ap0] = a_pf0.x;  As[nb][kc+1][ap0] = a_pf0.y;
            As[nb][kc+2][ap0] = a_pf0.z;  As[nb][kc+3][ap0] = a_pf0.w;
            As[nb][kc+0][ap1] = a_pf1.x;  As[nb][kc+1][ap1] = a_pf1.y;
            As[nb][kc+2][ap1] = a_pf1.z;  As[nb][kc+3][ap1] = a_pf1.w;
            if (has3) {
                As[nb][kc+0][ap2] = a_pf2.x;  As[nb][kc+1][ap2] = a_pf2.y;
                As[nb][kc+2][ap2] = a_pf2.z;  As[nb][kc+3][ap2] = a_pf2.w;
            }
            Bs[nb][kc+0][ar0] = b_pf.x;  Bs[nb][kc+1][ar0] = b_pf.y;
            Bs[nb][kc+2][ar0] = b_pf.z;  Bs[nb][kc+3][ar0] = b_pf.w;
            __syncthreads();
            buf = nb;
        }
    }

    // unpack pairs to scalars: rows lane*8 + 2p + {0,1}
    float acc[8][8];
#pragma unroll
    for (int p = 0; p < 4; p++)
#pragma unroll
        for (int j = 0; j < 8; j++)
            unpack2(acc2[p][j], acc[2*p][j], acc[2*p+1][j]);

    // write C + accumulate stats
    float s = 0.0f, ss = 0.0f;
#pragma unroll
    for (int i = 0; i < 8; i++) {
        const size_t base = (size_t)(row0 + lane * 8 + i) * F_ + (col0 + bcol);
        float4 c0 = make_float4(acc[i][0], acc[i][1], acc[i][2], acc[i][3]);
        float4 c1 = make_float4(acc[i][4], acc[i][5], acc[i][6], acc[i][7]);
        *(float4*)&g_project[base]     = c0;
        *(float4*)&g_project[base + 4] = c1;
#pragma unroll
        for (int j = 0; j < 8; j++) { float v = acc[i][j]; s += v; ss += v * v; }
    }
#pragma unroll
    for (int o = 16; o > 0; o >>= 1) {
        s  += __shfl_down_sync(0xffffffffu, s,  o);
        ss += __shfl_down_sync(0xffffffffu, ss, o);
    }
    __shared__ double wsum[12], wss[12];
    if ((tid & 31) == 0) { wsum[w] = (double)s; wss[w] = (double)ss; }
    __syncthreads();
    if (tid == 0) {
        double S = 0.0, SS = 0.0;
        for (int i = 0; i < 12; i++) { S += wsum[i]; SS += wss[i]; }
        const int bid = blockIdx.y * gridDim.x + blockIdx.x;
        g_part[bid][0] = S;
        g_part[bid][1] = SS;
    }
}

// ---------------------------------------------------------------------------
// Per-row top-k (exact radix select on monotone float keys) + reconstruction
// ---------------------------------------------------------------------------
__device__ __forceinline__ unsigned fkey(float v) {
    unsigned u = __float_as_uint(v);
    return (u & 0x80000000u) ? ~u : (u | 0x80000000u);
}

struct SelShared { int T; int nsel; int neq; };

__device__ void suffix_scan(unsigned* h, int NB) {
    const int tid = threadIdx.x;
    for (int off = 1; off < NB; off <<= 1) {
        unsigned v[8];
        int c = 0;
        for (int idx = tid; idx < NB; idx += NTH) {
            const int srcIdx = idx + off;
            v[c++] = (srcIdx < NB) ? h[srcIdx] : 0u;
        }
        __syncthreads();
        c = 0;
        for (int idx = tid; idx < NB; idx += NTH) h[idx] += v[c++];
        __syncthreads();
    }
}

__device__ int find_T(unsigned* h, int NB, unsigned K, int* sT) {
    const int tid = threadIdx.x;
    for (int idx = tid; idx < NB; idx += NTH)
        if (h[idx] >= K && (idx == NB - 1 || h[idx + 1] < K)) *sT = idx;
    __syncthreads();
    return *sT;
}

// exact top-K of keys sk[0..F_) -> indices in selIdx[0..K)
__device__ void select_topk(const unsigned* sk, unsigned* hist,
                            int* selIdx, int* eqIdx, int K, SelShared* sh)
{
    const int tid = threadIdx.x;
    const unsigned Ku = (unsigned)K;

    // round 1: key bits [31:20]
    for (int i = tid; i < 4096; i += NTH) hist[i] = 0u;
    __syncthreads();
    for (int i = tid; i < F_; i += NTH) atomicAdd(&hist[sk[i] >> 20], 1u);
    __syncthreads();
    suffix_scan(hist, 4096);
    const int T1 = find_T(hist, 4096, Ku, &sh->T);
    const unsigned nA1 = (T1 < 4095) ? hist[T1 + 1] : 0u;
    unsigned Kr = Ku - nA1;
    __syncthreads();

    // round 2: bits [19:8], restricted to top12 == T1
    for (int i = tid; i < 4096; i += NTH) hist[i] = 0u;
    __syncthreads();
    for (int i = tid; i < F_; i += NTH) {
        const unsigned k = sk[i];
        if ((int)(k >> 20) == T1) atomicAdd(&hist[(k >> 8) & 0xFFFu], 1u);
    }
    __syncthreads();
    suffix_scan(hist, 4096);
    const int T2 = find_T(hist, 4096, Kr, &sh->T);
    const unsigned nA2 = (T2 < 4095) ? hist[T2 + 1] : 0u;
    Kr -= nA2;
    __syncthreads();

    // round 3: bits [7:0], restricted to top24 == (T1<<12)|T2
    const unsigned pre24 = ((unsigned)T1 << 12) | (unsigned)T2;
    for (int i = tid; i < 256; i += NTH) hist[i] = 0u;
    __syncthreads();
    for (int i = tid; i < F_; i += NTH) {
        const unsigned k = sk[i];
        if ((k >> 8) == pre24) atomicAdd(&hist[k & 0xFFu], 1u);
    }
    __syncthreads();
    suffix_scan(hist, 256);
    const int T3 = find_T(hist, 256, Kr, &sh->T);
    const unsigned nA3 = (T3 < 255) ? hist[T3 + 1] : 0u;
    const int needEq = (int)(Kr - nA3);
    const unsigned kth = (pre24 << 8) | (unsigned)T3;
    __syncthreads();

    // collect: all keys > kth, plus needEq keys == kth (lowest index first)
    if (tid == 0) { sh->nsel = 0; sh->neq = 0; }
    __syncthreads();
    for (int i = tid; i < F_; i += NTH) {
        const unsigned k = sk[i];
        if (k > kth) {
            const int p = atomicAdd(&sh->nsel, 1);
            selIdx[p] = i;
        } else if (k == kth) {
            const int p = atomicAdd(&sh->neq, 1);
            if (p < 64) eqIdx[p] = i;
        }
    }
    __syncthreads();
    if (tid == 0) {
        int m = sh->neq; if (m > 64) m = 64;
        for (int a = 1; a < m; a++) {           // tiny insertion sort by index
            int v = eqIdx[a]; int c = a - 1;
            while (c >= 0 && eqIdx[c] > v) { eqIdx[c + 1] = eqIdx[c]; c--; }
            eqIdx[c + 1] = v;
        }
        const int base = sh->nsel;
        for (int a = 0; a < needEq; a++)
            selIdx[base + a] = (a < m) ? eqIdx[a] : eqIdx[0];
    }
    __syncthreads();
}

__global__ __launch_bounds__(NTH)
void row_kernel(const float* __restrict__ noise,
                const int*   __restrict__ last_usage,
                const float* __restrict__ lookup,
                const float* __restrict__ bias,
                float* __restrict__ out)
{
    extern __shared__ unsigned char smem_raw[];
    float*    sp     = (float*)smem_raw;                                  // F_
    unsigned* sk     = (unsigned*)(smem_raw + (size_t)F_ * 4);            // F_
    unsigned* hist   = (unsigned*)(smem_raw + (size_t)F_ * 8);            // 4096
    int*      selIdx = (int*)(smem_raw + (size_t)F_ * 8 + 4096 * 4);      // 256
    int*      eqIdx  = (int*)((char*)selIdx + 256 * 4);                   // 64

    __shared__ SelShared sh;
    __shared__ int   feats32[K1];
    __shared__ float w32[K1];
    __shared__ float uw[K2_];

    const int tid = threadIdx.x;
    const int b   = blockIdx.x;

    // load this row of project into smem
    const float* prow = g_project + (size_t)b * F_;
    for (int i = tid; i < F_; i += NTH) sp[i] = prow[i];

    // fuzz = std(project, ddof=1) * FUZZ_FACTOR(=1)
    const double S  = g_sum;
    const double SS = g_sumsq;
    const double N  = (double)B_ * (double)F_;
    const float fuzz = (float)sqrt((SS - S * S / N) / (N - 1.0));

    // ---- pass 1: top-32 of project ----
    __syncthreads();
    for (int i = tid; i < F_; i += NTH) sk[i] = fkey(sp[i]);
    __syncthreads();
    select_topk(sk, hist, selIdx, eqIdx, K1, &sh);
    for (int j = tid; j < K1; j += NTH) {
        feats32[j] = selIdx[j];
        w32[j]     = sp[selIdx[j]];
    }
    __syncthreads();

    // ---- pass 2: top-256 of fuzzed dead features ----
    const float* nrow = noise + (size_t)b * F_;
    for (int i = tid; i < F_; i += NTH)
        sk[i] = (last_usage[i] > DEAD_CUT) ? fkey(sp[i] + fuzz * nrow[i]) : 0u;
    __syncthreads();
    select_topk(sk, hist, selIdx, eqIdx, K2_, &sh);
    for (int j = tid; j < K2_; j += NTH) uw[j] = sp[selIdx[j]];   // weight = project value
    __syncthreads();

    // ---- reconstruction ----
    for (int d = tid; d < D_; d += NTH) {
        float a = bias[d];
#pragma unroll 8
        for (int k = 0; k < K1; k++)
            a += w32[k] * lookup[(size_t)feats32[k] * D_ + d];
        out[(size_t)b * D_ + d] = a;

        float a0 = 0.f, a1 = 0.f, a2 = 0.f, a3 = 0.f;
#pragma unroll 2
        for (int k = 0; k < K2_; k += 4) {
            a0 += uw[k + 0] * lookup[(size_t)selIdx[k + 0] * D_ + d];
            a1 += uw[k + 1] * lookup[(size_t)selIdx[k + 1] * D_ + d];
            a2 += uw[k + 2] * lookup[(size_t)selIdx[k + 2] * D_ + d];
            a3 += uw[k + 3] * lookup[(size_t)selIdx[k + 3] * D_ + d];
        }
        out[(size_t)B_ * D_ + (size_t)b * D_ + d] = (a0 + a1) + (a2 + a3);
    }
}

// ---------------------------------------------------------------------------
// Launch
// ---------------------------------------------------------------------------
extern "C" void kernel_launch(void* const* d_in, const int* in_sizes, int n_in,
                              void* d_out, int out_size)
{
    (void)in_sizes; (void)n_in; (void)out_size;
    const float* embed      = (const float*)d_in[0];
    const float* enc_bias   = (const float*)d_in[1];
    const float* enc_W      = (const float*)d_in[2];
    const float* lookup     = (const float*)d_in[3];
    const float* noise      = (const float*)d_in[4];
    const int*   last_usage = (const int*)  d_in[5];
    float* out = (float*)d_out;

    const size_t smem_bytes = (size_t)F_ * 8 + 4096 * 4 + 256 * 4 + 64 * 4; // 214272
    cudaFuncSetAttribute(row_kernel,
                         cudaFuncAttributeMaxDynamicSharedMemorySize,
                         (int)smem_bytes);

    pre_kernel<<<(B_ * D_) / 512, 512>>>(embed, enc_bias);
    gemm_kernel<<<dim3(GRID_X, GRID_Y), GTH>>>(enc_W);
    reduce_stats_kernel<<<1, 512>>>();
    row_kernel<<<B_, NTH, smem_bytes>>>(noise, last_usage, lookup, enc_bias, out);
}

// round 16
// speedup vs baseline: 1.0590x; 1.0590x over previous
#include <cuda_runtime.h>
#include <math.h>

#define B_   4096
#define D_   1024
#define F_   24576
#define K1   32      /* TOPK */
#define K2_  256     /* DEAD_TOPK */
#define KSEL (K1 + K2_)   /* 288 */
#define DEAD_CUT 100000
#define NTH  512     /* threads in selection kernel */

#define GRID_X (F_ / 128)          /* 192 */
#define GRID_Y (B_ / 128)          /* 32  */
#define NBLK   (GRID_X * GRID_Y)   /* 6144 */

// ---------------------------------------------------------------------------
// Scratch (device globals: no cudaMalloc allowed)
// ---------------------------------------------------------------------------
__device__ float  g_project[(size_t)B_ * (size_t)F_];   // 402 MB
__device__ double g_part[NBLK][2];                      // per-CTA (sum, sumsq)
__device__ double g_sum;
__device__ double g_sumsq;
__device__ int    g_selIdx[(size_t)B_ * KSEL];          // 4.7 MB
__device__ float  g_selW[(size_t)B_ * KSEL];            // 4.7 MB

// Deterministic reduction of per-CTA partials -> g_sum / g_sumsq.
__global__ __launch_bounds__(512)
void reduce_stats_kernel() {
    const int tid = threadIdx.x;
    double s = 0.0, ss = 0.0;
    for (int i = tid; i < NBLK; i += 512) {
        s  += g_part[i][0];
        ss += g_part[i][1];
    }
    __shared__ double sh_s[512], sh_ss[512];
    sh_s[tid] = s; sh_ss[tid] = ss;
    __syncthreads();
    for (int off = 256; off > 0; off >>= 1) {
        if (tid < off) {
            sh_s[tid]  += sh_s[tid + off];
            sh_ss[tid] += sh_ss[tid + off];
        }
        __syncthreads();
    }
    if (tid == 0) { g_sum = sh_s[0]; g_sumsq = sh_ss[0]; }
}

// ---------------------------------------------------------------------------
// packed f32x2 helpers (SASS FFMA2). Each half is an IEEE fp32 FMA.
// ---------------------------------------------------------------------------
__device__ __forceinline__ void fma2(unsigned long long& d,
                                     unsigned long long a,
                                     unsigned long long b) {
    asm("fma.rn.f32x2 %0, %1, %2, %0;" : "+l"(d) : "l"(a), "l"(b));
}
__device__ __forceinline__ void add2(unsigned long long& d,
                                     unsigned long long a) {
    asm("add.rn.f32x2 %0, %0, %1;" : "+l"(d) : "l"(a));
}
__device__ __forceinline__ unsigned long long dupf(float x) {
    unsigned long long r;
    asm("mov.b64 %0, {%1, %1};" : "=l"(r) : "f"(x));
    return r;
}
__device__ __forceinline__ void unpack2(unsigned long long v, float& lo, float& hi) {
    asm("mov.b64 {%0, %1}, %2;" : "=f"(lo), "=f"(hi) : "l"(v));
}

// XOR swizzle of 16-byte chunks within a 128-float Bs row (R13/R14):
// chunk q -> q ^ ((q>>3)&1). Conflict-free for the 32-B-stride fragment loads.
__device__ __forceinline__ int bswiz(int c) {
    int q = c >> 2;
    q ^= (q >> 3) & 1;
    return (q << 2) | (c & 3);
}

// ---------------------------------------------------------------------------
// SGEMM (R14 version, verbatim): project[b,f] = sum_d (embed[b,d]-bias[d])*W[f,d]
// 128x128 tile, BK=16, 512 threads, 4x8 micro-tile, FFMA2, swizzled Bs.
// ---------------------------------------------------------------------------
#define BM 128
#define BN 128
#define BK 16

__global__ __launch_bounds__(512, 1)
void gemm_kernel(const float* __restrict__ embed,
                 const float* __restrict__ bias,
                 const float* __restrict__ W)
{
    __shared__ __align__(16) float As[2][BK][BM];
    __shared__ __align__(16) float Bs[2][BK][BN];

    const int tid  = threadIdx.x;
    const int row0 = blockIdx.y * BM;
    const int col0 = blockIdx.x * BN;

    const int ar = tid >> 2;
    const int aq = tid & 3;
    const int brs = bswiz(ar);

    const float* Ap = embed + (size_t)(row0 + ar) * D_ + aq * 4;
    const float* Bp = W     + (size_t)(col0 + ar) * D_ + aq * 4;

    unsigned long long acc2[2][8];
#pragma unroll
    for (int p = 0; p < 2; p++)
#pragma unroll
        for (int j = 0; j < 8; j++) acc2[p][j] = 0ull;

    float4 a0, b0, bb;
    a0 = *(const float4*)(Ap);
    b0 = *(const float4*)(Bp);
    bb = *(const float4*)(bias + aq * 4);

    int buf = 0;
    {
        const int kc = aq * 4;
        As[0][kc+0][ar] = a0.x - bb.x;  As[0][kc+1][ar] = a0.y - bb.y;
        As[0][kc+2][ar] = a0.z - bb.z;  As[0][kc+3][ar] = a0.w - bb.w;
        Bs[0][kc+0][brs] = b0.x;  Bs[0][kc+1][brs] = b0.y;
        Bs[0][kc+2][brs] = b0.z;  Bs[0][kc+3][brs] = b0.w;
    }
    __syncthreads();

    const int ty = tid >> 4;
    const int tx = tid & 15;
    const int NT = D_ / BK;

    const int txs0 = bswiz(tx * 8);
    const int txs1 = bswiz(tx * 8 + 4);

    for (int t = 0; t < NT; t++) {
        if (t + 1 < NT) {
            const int k0 = (t + 1) * BK;
            a0 = *(const float4*)(Ap + k0);
            b0 = *(const float4*)(Bp + k0);
            bb = *(const float4*)(bias + k0 + aq * 4);
        }
        unsigned long long ts2[2][8];
#pragma unroll
        for (int p = 0; p < 2; p++)
#pragma unroll
            for (int j = 0; j < 8; j++) ts2[p][j] = 0ull;

#pragma unroll
        for (int kk = 0; kk < BK; kk++) {
            ulonglong2 pa = *(const ulonglong2*)&As[buf][kk][ty * 4];
            float4 f0 = *(const float4*)&Bs[buf][kk][txs0];
            float4 f1 = *(const float4*)&Bs[buf][kk][txs1];
            unsigned long long b2[8] = {
                dupf(f0.x), dupf(f0.y), dupf(f0.z), dupf(f0.w),
                dupf(f1.x), dupf(f1.y), dupf(f1.z), dupf(f1.w)
            };
#pragma unroll
            for (int j = 0; j < 8; j++) fma2(ts2[0][j], pa.x, b2[j]);
#pragma unroll
            for (int j = 0; j < 8; j++) fma2(ts2[1][j], pa.y, b2[j]);
        }
#pragma unroll
        for (int p = 0; p < 2; p++)
#pragma unroll
            for (int j = 0; j < 8; j++)
                add2(acc2[p][j], ts2[p][j]);

        if (t + 1 < NT) {
            const int nb = buf ^ 1;
            const int kc = aq * 4;
            As[nb][kc+0][ar] = a0.x - bb.x;  As[nb][kc+1][ar] = a0.y - bb.y;
            As[nb][kc+2][ar] = a0.z - bb.z;  As[nb][kc+3][ar] = a0.w - bb.w;
            Bs[nb][kc+0][brs] = b0.x;  Bs[nb][kc+1][brs] = b0.y;
            Bs[nb][kc+2][brs] = b0.z;  Bs[nb][kc+3][brs] = b0.w;
            __syncthreads();
            buf = nb;
        }
    }

    float acc[4][8];
#pragma unroll
    for (int p = 0; p < 2; p++)
#pragma unroll
        for (int j = 0; j < 8; j++)
            unpack2(acc2[p][j], acc[2*p][j], acc[2*p+1][j]);

    float s = 0.0f, ss = 0.0f;
#pragma unroll
    for (int i = 0; i < 4; i++) {
        const size_t base = (size_t)(row0 + ty * 4 + i) * F_ + (col0 + tx * 8);
        float4 c0 = make_float4(acc[i][0], acc[i][1], acc[i][2], acc[i][3]);
        float4 c1 = make_float4(acc[i][4], acc[i][5], acc[i][6], acc[i][7]);
        *(float4*)&g_project[base]     = c0;
        *(float4*)&g_project[base + 4] = c1;
#pragma unroll
        for (int j = 0; j < 8; j++) { float v = acc[i][j]; s += v; ss += v * v; }
    }
#pragma unroll
    for (int o = 16; o > 0; o >>= 1) {
        s  += __shfl_down_sync(0xffffffffu, s,  o);
        ss += __shfl_down_sync(0xffffffffu, ss, o);
    }
    __shared__ double wsum[16], wss[16];
    const int w = tid >> 5, l = tid & 31;
    if (l == 0) { wsum[w] = (double)s; wss[w] = (double)ss; }
    __syncthreads();
    if (tid == 0) {
        double S = 0.0, SS = 0.0;
        for (int i = 0; i < 16; i++) { S += wsum[i]; SS += wss[i]; }
        const int bid = blockIdx.y * gridDim.x + blockIdx.x;
        g_part[bid][0] = S;
        g_part[bid][1] = SS;
    }
}

// ---------------------------------------------------------------------------
// Per-row top-k (exact radix select on monotone float keys)
// ---------------------------------------------------------------------------
__device__ __forceinline__ unsigned fkey(float v) {
    unsigned u = __float_as_uint(v);
    return (u & 0x80000000u) ? ~u : (u | 0x80000000u);
}

struct SelShared { int T; int nsel; int neq; };

__device__ void suffix_scan(unsigned* h, int NB) {
    const int tid = threadIdx.x;
    for (int off = 1; off < NB; off <<= 1) {
        unsigned v[8];
        int c = 0;
        for (int idx = tid; idx < NB; idx += NTH) {
            const int srcIdx = idx + off;
            v[c++] = (srcIdx < NB) ? h[srcIdx] : 0u;
        }
        __syncthreads();
        c = 0;
        for (int idx = tid; idx < NB; idx += NTH) h[idx] += v[c++];
        __syncthreads();
    }
}

__device__ int find_T(unsigned* h, int NB, unsigned K, int* sT) {
    const int tid = threadIdx.x;
    for (int idx = tid; idx < NB; idx += NTH)
        if (h[idx] >= K && (idx == NB - 1 || h[idx + 1] < K)) *sT = idx;
    __syncthreads();
    return *sT;
}

// exact top-K of keys sk[0..F_) -> indices in selIdx[0..K)
__device__ void select_topk(const unsigned* sk, unsigned* hist,
                            int* selIdx, int* eqIdx, int K, SelShared* sh)
{
    const int tid = threadIdx.x;
    const unsigned Ku = (unsigned)K;

    // round 1: key bits [31:20] — WARP-AGGREGATED atomics. Normal-distributed
    // keys collapse into ~50 exponent bins; match_any turns ~32 colliding
    // atomics into 1 per distinct bin per warp. Counts identical.
    for (int i = tid; i < 4096; i += NTH) hist[i] = 0u;
    __syncthreads();
    for (int i = tid; i < F_; i += NTH) {
        const unsigned bin = sk[i] >> 20;
        const unsigned mask = __match_any_sync(0xffffffffu, bin);
        if ((tid & 31) == (__ffs(mask) - 1))
            atomicAdd(&hist[bin], (unsigned)__popc(mask));
    }
    __syncthreads();
    suffix_scan(hist, 4096);
    const int T1 = find_T(hist, 4096, Ku, &sh->T);
    const unsigned nA1 = (T1 < 4095) ? hist[T1 + 1] : 0u;
    unsigned Kr = Ku - nA1;
    __syncthreads();

    // round 2: bits [19:8], restricted to top12 == T1 (mantissa bits: spread)
    for (int i = tid; i < 4096; i += NTH) hist[i] = 0u;
    __syncthreads();
    for (int i = tid; i < F_; i += NTH) {
        const unsigned k = sk[i];
        if ((int)(k >> 20) == T1) atomicAdd(&hist[(k >> 8) & 0xFFFu], 1u);
    }
    __syncthreads();
    suffix_scan(hist, 4096);
    const int T2 = find_T(hist, 4096, Kr, &sh->T);
    const unsigned nA2 = (T2 < 4095) ? hist[T2 + 1] : 0u;
    Kr -= nA2;
    __syncthreads();

    // round 3: bits [7:0], restricted to top24 == (T1<<12)|T2
    const unsigned pre24 = ((unsigned)T1 << 12) | (unsigned)T2;
    for (int i = tid; i < 256; i += NTH) hist[i] = 0u;
    __syncthreads();
    for (int i = tid; i < F_; i += NTH) {
        const unsigned k = sk[i];
        if ((k >> 8) == pre24) atomicAdd(&hist[k & 0xFFu], 1u);
    }
    __syncthreads();
    suffix_scan(hist, 256);
    const int T3 = find_T(hist, 256, Kr, &sh->T);
    const unsigned nA3 = (T3 < 255) ? hist[T3 + 1] : 0u;
    const int needEq = (int)(Kr - nA3);
    const unsigned kth = (pre24 << 8) | (unsigned)T3;
    __syncthreads();

    // collect: all keys > kth, plus needEq keys == kth (lowest index first)
    if (tid == 0) { sh->nsel = 0; sh->neq = 0; }
    __syncthreads();
    for (int i = tid; i < F_; i += NTH) {
        const unsigned k = sk[i];
        if (k > kth) {
            const int p = atomicAdd(&sh->nsel, 1);
            selIdx[p] = i;
        } else if (k == kth) {
            const int p = atomicAdd(&sh->neq, 1);
            if (p < 64) eqIdx[p] = i;
        }
    }
    __syncthreads();
    if (tid == 0) {
        int m = sh->neq; if (m > 64) m = 64;
        for (int a = 1; a < m; a++) {
            int v = eqIdx[a]; int c = a - 1;
            while (c >= 0 && eqIdx[c] > v) { eqIdx[c + 1] = eqIdx[c]; c--; }
            eqIdx[c + 1] = v;
        }
        const int base = sh->nsel;
        for (int a = 0; a < needEq; a++)
            selIdx[base + a] = (a < m) ? eqIdx[a] : eqIdx[0];
    }
    __syncthreads();
}

// ---------------------------------------------------------------------------
// Selection kernel: both top-k passes; writes (idx, weight) pairs to global.
// ---------------------------------------------------------------------------
__global__ __launch_bounds__(NTH)
void select_kernel(const float* __restrict__ noise,
                   const int*   __restrict__ last_usage)
{
    extern __shared__ unsigned char smem_raw[];
    float*    sp     = (float*)smem_raw;                                  // F_
    unsigned* sk     = (unsigned*)(smem_raw + (size_t)F_ * 4);            // F_
    unsigned* hist   = (unsigned*)(smem_raw + (size_t)F_ * 8);            // 4096
    int*      selIdx = (int*)(smem_raw + (size_t)F_ * 8 + 4096 * 4);      // 256
    int*      eqIdx  = (int*)((char*)selIdx + 256 * 4);                   // 64

    __shared__ SelShared sh;

    const int tid = threadIdx.x;
    const int b   = blockIdx.x;

    const float* prow = g_project + (size_t)b * F_;
    for (int i = tid; i < F_; i += NTH) sp[i] = prow[i];

    // fuzz = std(project, ddof=1) * FUZZ_FACTOR(=1)
    const double S  = g_sum;
    const double SS = g_sumsq;
    const double N  = (double)B_ * (double)F_;
    const float fuzz = (float)sqrt((SS - S * S / N) / (N - 1.0));

    // ---- pass 1: top-32 of project ----
    __syncthreads();
    for (int i = tid; i < F_; i += NTH) sk[i] = fkey(sp[i]);
    __syncthreads();
    select_topk(sk, hist, selIdx, eqIdx, K1, &sh);
    for (int j = tid; j < K1; j += NTH) {
        g_selIdx[(size_t)b * KSEL + j] = selIdx[j];
        g_selW[(size_t)b * KSEL + j]   = sp[selIdx[j]];
    }
    __syncthreads();

    // ---- pass 2: top-256 of fuzzed dead features ----
    const float* nrow = noise + (size_t)b * F_;
    for (int i = tid; i < F_; i += NTH)
        sk[i] = (last_usage[i] > DEAD_CUT) ? fkey(sp[i] + fuzz * nrow[i]) : 0u;
    __syncthreads();
    select_topk(sk, hist, selIdx, eqIdx, K2_, &sh);
    for (int j = tid; j < K2_; j += NTH) {
        g_selIdx[(size_t)b * KSEL + K1 + j] = selIdx[j];
        g_selW[(size_t)b * KSEL + K1 + j]   = sp[selIdx[j]];
    }
}

// ---------------------------------------------------------------------------
// Reconstruction kernel: 2 CTAs per row, 512 threads, 1 d each.
// Tiny smem -> multiple CTAs/SM -> gathers run at L2 bandwidth.
// ---------------------------------------------------------------------------
__global__ __launch_bounds__(512)
void recon_kernel(const float* __restrict__ lookup,
                  const float* __restrict__ bias,
                  float* __restrict__ out)
{
    __shared__ int   sidx[KSEL];
    __shared__ float sw[KSEL];

    const int tid  = threadIdx.x;
    const int b    = blockIdx.x >> 1;
    const int half = blockIdx.x & 1;

    if (tid < KSEL) {
        sidx[tid] = g_selIdx[(size_t)b * KSEL + tid];
        sw[tid]   = g_selW[(size_t)b * KSEL + tid];
    }
    __syncthreads();

    const int d = half * 512 + tid;

    float a = bias[d];
#pragma unroll 8
    for (int k = 0; k < K1; k++)
        a += sw[k] * lookup[(size_t)sidx[k] * D_ + d];
    out[(size_t)b * D_ + d] = a;

    float a0 = 0.f, a1 = 0.f, a2 = 0.f, a3 = 0.f;
#pragma unroll 4
    for (int k = 0; k < K2_; k += 4) {
        a0 += sw[K1 + k + 0] * lookup[(size_t)sidx[K1 + k + 0] * D_ + d];
        a1 += sw[K1 + k + 1] * lookup[(size_t)sidx[K1 + k + 1] * D_ + d];
        a2 += sw[K1 + k + 2] * lookup[(size_t)sidx[K1 + k + 2] * D_ + d];
        a3 += sw[K1 + k + 3] * lookup[(size_t)sidx[K1 + k + 3] * D_ + d];
    }
    out[(size_t)B_ * D_ + (size_t)b * D_ + d] = (a0 + a1) + (a2 + a3);
}

// ---------------------------------------------------------------------------
// Launch
// ---------------------------------------------------------------------------
extern "C" void kernel_launch(void* const* d_in, const int* in_sizes, int n_in,
                              void* d_out, int out_size)
{
    (void)in_sizes; (void)n_in; (void)out_size;
    const float* embed      = (const float*)d_in[0];
    const float* enc_bias   = (const float*)d_in[1];
    const float* enc_W      = (const float*)d_in[2];
    const float* lookup     = (const float*)d_in[3];
    const float* noise      = (const float*)d_in[4];
    const int*   last_usage = (const int*)  d_in[5];
    float* out = (float*)d_out;

    const size_t smem_bytes = (size_t)F_ * 8 + 4096 * 4 + 256 * 4 + 64 * 4; // 214272
    cudaFuncSetAttribute(select_kernel,
                         cudaFuncAttributeMaxDynamicSharedMemorySize,
                         (int)smem_bytes);

    gemm_kernel<<<dim3(GRID_X, GRID_Y), 512>>>(embed, enc_bias, enc_W);
    reduce_stats_kernel<<<1, 512>>>();
    select_kernel<<<B_, NTH, smem_bytes>>>(noise, last_usage);
    recon_kernel<<<B_ * 2, 512>>>(lookup, enc_bias, out);
}

// round 17
// speedup vs baseline: 1.2678x; 1.1972x over previous
#include <cuda_runtime.h>
#include <math.h>

#define B_   4096
#define D_   1024
#define F_   24576
#define K1   32      /* TOPK */
#define K2_  256     /* DEAD_TOPK */
#define KSEL (K1 + K2_)   /* 288 */
#define DEAD_CUT 100000
#define NTH  512     /* threads in selection kernel */

#define GRID_X (F_ / 128)          /* 192 */
#define GRID_Y (B_ / 128)          /* 32  */
#define NBLK   (GRID_X * GRID_Y)   /* 6144 */

// ---------------------------------------------------------------------------
// Scratch (device globals: no cudaMalloc allowed)
// ---------------------------------------------------------------------------
__device__ float  g_project[(size_t)B_ * (size_t)F_];   // 402 MB
__device__ double g_part[NBLK][2];                      // per-CTA (sum, sumsq)
__device__ double g_sum;
__device__ double g_sumsq;
__device__ int    g_selIdx[(size_t)B_ * KSEL];          // 4.7 MB
__device__ float  g_selW[(size_t)B_ * KSEL];            // 4.7 MB

// Deterministic reduction of per-CTA partials -> g_sum / g_sumsq.
__global__ __launch_bounds__(512)
void reduce_stats_kernel() {
    const int tid = threadIdx.x;
    double s = 0.0, ss = 0.0;
    for (int i = tid; i < NBLK; i += 512) {
        s  += g_part[i][0];
        ss += g_part[i][1];
    }
    __shared__ double sh_s[512], sh_ss[512];
    sh_s[tid] = s; sh_ss[tid] = ss;
    __syncthreads();
    for (int off = 256; off > 0; off >>= 1) {
        if (tid < off) {
            sh_s[tid]  += sh_s[tid + off];
            sh_ss[tid] += sh_ss[tid + off];
        }
        __syncthreads();
    }
    if (tid == 0) { g_sum = sh_s[0]; g_sumsq = sh_ss[0]; }
}

// ---------------------------------------------------------------------------
// packed f32x2 helpers (SASS FFMA2). Each half is an IEEE fp32 FMA.
// ---------------------------------------------------------------------------
__device__ __forceinline__ void fma2(unsigned long long& d,
                                     unsigned long long a,
                                     unsigned long long b) {
    asm("fma.rn.f32x2 %0, %1, %2, %0;" : "+l"(d) : "l"(a), "l"(b));
}
__device__ __forceinline__ void add2(unsigned long long& d,
                                     unsigned long long a) {
    asm("add.rn.f32x2 %0, %0, %1;" : "+l"(d) : "l"(a));
}
__device__ __forceinline__ unsigned long long dupf(float x) {
    unsigned long long r;
    asm("mov.b64 %0, {%1, %1};" : "=l"(r) : "f"(x));
    return r;
}
__device__ __forceinline__ void unpack2(unsigned long long v, float& lo, float& hi) {
    asm("mov.b64 {%0, %1}, %2;" : "=f"(lo), "=f"(hi) : "l"(v));
}

// ---------------------------------------------------------------------------
// SGEMM: project[b,f] = sum_d (embed[b,d]-bias[d]) * W[f,d]
// 128x128 tile, BK=16, 512 threads, FFMA2 mainloop.
// NEW mapping: warp = column-group -> B fragment loads are warp-BROADCAST
// (1 cyc each); lane = row-group -> A load is one consecutive conflict-free
// LDS.128. smem drops 192 -> 96 cyc/kk, below the 128-cyc FFMA2 bound.
// Pure thread->element remap: per-element FP op sequence identical -> bit-exact.
// ---------------------------------------------------------------------------
#define BM 128
#define BN 128
#define BK 16

__global__ __launch_bounds__(512, 1)
void gemm_kernel(const float* __restrict__ embed,
                 const float* __restrict__ bias,
                 const float* __restrict__ W)
{
    __shared__ __align__(16) float As[2][BK][BM];
    __shared__ __align__(16) float Bs[2][BK][BN];

    const int tid  = threadIdx.x;
    const int row0 = blockIdx.y * BM;
    const int col0 = blockIdx.x * BN;

    // loader mapping: each thread loads ONE float4 of A and of B per slab
    const int ar = tid >> 2;     // 0..127
    const int aq = tid & 3;      // float4 index within 16-wide k slab

    const float* Ap = embed + (size_t)(row0 + ar) * D_ + aq * 4;
    const float* Bp = W     + (size_t)(col0 + ar) * D_ + aq * 4;

    // compute mapping: warp -> columns, lane -> rows
    const int w    = tid >> 5;   // 0..15 : cols w*8 .. w*8+7
    const int lane = tid & 31;   // 0..31 : rows lane*4 .. lane*4+3

    // paired accumulators: acc2[p][j] holds rows (lane*4+2p, lane*4+2p+1)
    unsigned long long acc2[2][8];
#pragma unroll
    for (int p = 0; p < 2; p++)
#pragma unroll
        for (int j = 0; j < 8; j++) acc2[p][j] = 0ull;

    float4 a0, b0, bb;
    a0 = *(const float4*)(Ap);
    b0 = *(const float4*)(Bp);
    bb = *(const float4*)(bias + aq * 4);

    int buf = 0;
    {
        const int kc = aq * 4;
        As[0][kc+0][ar] = a0.x - bb.x;  As[0][kc+1][ar] = a0.y - bb.y;
        As[0][kc+2][ar] = a0.z - bb.z;  As[0][kc+3][ar] = a0.w - bb.w;
        Bs[0][kc+0][ar] = b0.x;  Bs[0][kc+1][ar] = b0.y;
        Bs[0][kc+2][ar] = b0.z;  Bs[0][kc+3][ar] = b0.w;
    }
    __syncthreads();

    const int NT = D_ / BK;   // 64
    const int bcol = w * 8;

    for (int t = 0; t < NT; t++) {
        if (t + 1 < NT) {
            const int k0 = (t + 1) * BK;
            a0 = *(const float4*)(Ap + k0);
            b0 = *(const float4*)(Bp + k0);
            bb = *(const float4*)(bias + k0 + aq * 4);
        }
        // per-tile partial sums (fresh registers -> short rounding chains)
        unsigned long long ts2[2][8];
#pragma unroll
        for (int p = 0; p < 2; p++)
#pragma unroll
            for (int j = 0; j < 8; j++) ts2[p][j] = 0ull;

#pragma unroll
        for (int kk = 0; kk < BK; kk++) {
            // A: one consecutive LDS.128 -> rows lane*4..+3 = 2 pairs
            ulonglong2 pa = *(const ulonglong2*)&As[buf][kk][lane * 4];
            // B: two warp-broadcast LDS.128 (all lanes same address)
            float4 f0 = *(const float4*)&Bs[buf][kk][bcol];
            float4 f1 = *(const float4*)&Bs[buf][kk][bcol + 4];
            unsigned long long b2[8] = {
                dupf(f0.x), dupf(f0.y), dupf(f0.z), dupf(f0.w),
                dupf(f1.x), dupf(f1.y), dupf(f1.z), dupf(f1.w)
            };
#pragma unroll
            for (int j = 0; j < 8; j++) fma2(ts2[0][j], pa.x, b2[j]);
#pragma unroll
            for (int j = 0; j < 8; j++) fma2(ts2[1][j], pa.y, b2[j]);
        }
#pragma unroll
        for (int p = 0; p < 2; p++)
#pragma unroll
            for (int j = 0; j < 8; j++)
                add2(acc2[p][j], ts2[p][j]);

        if (t + 1 < NT) {
            const int nb = buf ^ 1;
            const int kc = aq * 4;
            As[nb][kc+0][ar] = a0.x - bb.x;  As[nb][kc+1][ar] = a0.y - bb.y;
            As[nb][kc+2][ar] = a0.z - bb.z;  As[nb][kc+3][ar] = a0.w - bb.w;
            Bs[nb][kc+0][ar] = b0.x;  Bs[nb][kc+1][ar] = b0.y;
            Bs[nb][kc+2][ar] = b0.z;  Bs[nb][kc+3][ar] = b0.w;
            __syncthreads();
            buf = nb;
        }
    }

    // unpack pairs to scalars: rows lane*4 + 2p + {0,1}
    float acc[4][8];
#pragma unroll
    for (int p = 0; p < 2; p++)
#pragma unroll
        for (int j = 0; j < 8; j++)
            unpack2(acc2[p][j], acc[2*p][j], acc[2*p+1][j]);

    // write C + accumulate stats
    float s = 0.0f, ss = 0.0f;
#pragma unroll
    for (int i = 0; i < 4; i++) {
        const size_t base = (size_t)(row0 + lane * 4 + i) * F_ + (col0 + bcol);
        float4 c0 = make_float4(acc[i][0], acc[i][1], acc[i][2], acc[i][3]);
        float4 c1 = make_float4(acc[i][4], acc[i][5], acc[i][6], acc[i][7]);
        *(float4*)&g_project[base]     = c0;
        *(float4*)&g_project[base + 4] = c1;
#pragma unroll
        for (int j = 0; j < 8; j++) { float v = acc[i][j]; s += v; ss += v * v; }
    }
#pragma unroll
    for (int o = 16; o > 0; o >>= 1) {
        s  += __shfl_down_sync(0xffffffffu, s,  o);
        ss += __shfl_down_sync(0xffffffffu, ss, o);
    }
    __shared__ double wsum[16], wss[16];
    if ((tid & 31) == 0) { wsum[w] = (double)s; wss[w] = (double)ss; }
    __syncthreads();
    if (tid == 0) {
        double S = 0.0, SS = 0.0;
        for (int i = 0; i < 16; i++) { S += wsum[i]; SS += wss[i]; }
        const int bid = blockIdx.y * gridDim.x + blockIdx.x;
        g_part[bid][0] = S;
        g_part[bid][1] = SS;
    }
}

// ---------------------------------------------------------------------------
// Per-row top-k (exact radix select on monotone float keys)
// Digits 11/11/10 (hist <= 2048 bins -> 8KB) so TWO CTAs fit per SM.
// kth threshold is the exact full-32-bit k-th key; tie handling identical.
// ---------------------------------------------------------------------------
__device__ __forceinline__ unsigned fkey(float v) {
    unsigned u = __float_as_uint(v);
    return (u & 0x80000000u) ? ~u : (u | 0x80000000u);
}
// exact inverse of fkey (bit-exact float recovery from key)
__device__ __forceinline__ float ikey(unsigned k) {
    unsigned u = (k & 0x80000000u) ? (k & 0x7fffffffu) : ~k;
    return __uint_as_float(u);
}

struct SelShared { int T; int nsel; int neq; };

__device__ void suffix_scan(unsigned* h, int NB) {
    const int tid = threadIdx.x;
    for (int off = 1; off < NB; off <<= 1) {
        unsigned v[4];
        int c = 0;
        for (int idx = tid; idx < NB; idx += NTH) {
            const int srcIdx = idx + off;
            v[c++] = (srcIdx < NB) ? h[srcIdx] : 0u;
        }
        __syncthreads();
        c = 0;
        for (int idx = tid; idx < NB; idx += NTH) h[idx] += v[c++];
        __syncthreads();
    }
}

__device__ int find_T(unsigned* h, int NB, unsigned K, int* sT) {
    const int tid = threadIdx.x;
    for (int idx = tid; idx < NB; idx += NTH)
        if (h[idx] >= K && (idx == NB - 1 || h[idx + 1] < K)) *sT = idx;
    __syncthreads();
    return *sT;
}

// exact top-K of keys sk[0..F_) -> indices in selIdx[0..K)
__device__ void select_topk(const unsigned* sk, unsigned* hist,
                            int* selIdx, int* eqIdx, int K, SelShared* sh)
{
    const int tid = threadIdx.x;
    const unsigned Ku = (unsigned)K;

    // round 1: key bits [31:21] (2048 bins) — warp-aggregated atomics
    for (int i = tid; i < 2048; i += NTH) hist[i] = 0u;
    __syncthreads();
    for (int i = tid; i < F_; i += NTH) {
        const unsigned bin = sk[i] >> 21;
        const unsigned mask = __match_any_sync(0xffffffffu, bin);
        if ((tid & 31) == (__ffs(mask) - 1))
            atomicAdd(&hist[bin], (unsigned)__popc(mask));
    }
    __syncthreads();
    suffix_scan(hist, 2048);
    const int T1 = find_T(hist, 2048, Ku, &sh->T);
    const unsigned nA1 = (T1 < 2047) ? hist[T1 + 1] : 0u;
    unsigned Kr = Ku - nA1;
    __syncthreads();

    // round 2: bits [20:10], restricted to top11 == T1
    for (int i = tid; i < 2048; i += NTH) hist[i] = 0u;
    __syncthreads();
    for (int i = tid; i < F_; i += NTH) {
        const unsigned k = sk[i];
        if ((int)(k >> 21) == T1) atomicAdd(&hist[(k >> 10) & 0x7FFu], 1u);
    }
    __syncthreads();
    suffix_scan(hist, 2048);
    const int T2 = find_T(hist, 2048, Kr, &sh->T);
    const unsigned nA2 = (T2 < 2047) ? hist[T2 + 1] : 0u;
    Kr -= nA2;
    __syncthreads();

    // round 3: bits [9:0] (1024 bins), restricted to top22 == (T1<<11)|T2
    const unsigned pre22 = ((unsigned)T1 << 11) | (unsigned)T2;
    for (int i = tid; i < 1024; i += NTH) hist[i] = 0u;
    __syncthreads();
    for (int i = tid; i < F_; i += NTH) {
        const unsigned k = sk[i];
        if ((k >> 10) == pre22) atomicAdd(&hist[k & 0x3FFu], 1u);
    }
    __syncthreads();
    suffix_scan(hist, 1024);
    const int T3 = find_T(hist, 1024, Kr, &sh->T);
    const unsigned nA3 = (T3 < 1023) ? hist[T3 + 1] : 0u;
    const int needEq = (int)(Kr - nA3);
    const unsigned kth = (pre22 << 10) | (unsigned)T3;
    __syncthreads();

    // collect: all keys > kth, plus needEq keys == kth (lowest index first)
    if (tid == 0) { sh->nsel = 0; sh->neq = 0; }
    __syncthreads();
    for (int i = tid; i < F_; i += NTH) {
        const unsigned k = sk[i];
        if (k > kth) {
            const int p = atomicAdd(&sh->nsel, 1);
            selIdx[p] = i;
        } else if (k == kth) {
            const int p = atomicAdd(&sh->neq, 1);
            if (p < 64) eqIdx[p] = i;
        }
    }
    __syncthreads();
    if (tid == 0) {
        int m = sh->neq; if (m > 64) m = 64;
        for (int a = 1; a < m; a++) {
            int v = eqIdx[a]; int c = a - 1;
            while (c >= 0 && eqIdx[c] > v) { eqIdx[c + 1] = eqIdx[c]; c--; }
            eqIdx[c + 1] = v;
        }
        const int base = sh->nsel;
        for (int a = 0; a < needEq; a++)
            selIdx[base + a] = (a < m) ? eqIdx[a] : eqIdx[0];
    }
    __syncthreads();
}

// ---------------------------------------------------------------------------
// Selection kernel: keys-only in smem (105 KB) -> 2 CTAs/SM.
// Pass-1 weights recovered bit-exactly by inverting keys; pass-2 weights
// read from global project (scattered, few hundred loads).
// ---------------------------------------------------------------------------
__global__ __launch_bounds__(NTH)
void select_kernel(const float* __restrict__ noise,
                   const int*   __restrict__ last_usage)
{
    extern __shared__ unsigned char smem_raw[];
    unsigned* sk     = (unsigned*)smem_raw;                               // F_
    unsigned* hist   = (unsigned*)(smem_raw + (size_t)F_ * 4);            // 2048
    int*      selIdx = (int*)(smem_raw + (size_t)F_ * 4 + 2048 * 4);      // 256
    int*      eqIdx  = (int*)((char*)selIdx + 256 * 4);                   // 64

    __shared__ SelShared sh;

    const int tid = threadIdx.x;
    const int b   = blockIdx.x;

    const float* prow = g_project + (size_t)b * F_;

    // fuzz = std(project, ddof=1) * FUZZ_FACTOR(=1)
    const double S  = g_sum;
    const double SS = g_sumsq;
    const double N  = (double)B_ * (double)F_;
    const float fuzz = (float)sqrt((SS - S * S / N) / (N - 1.0));

    // ---- pass 1: top-32 of project ----
    for (int i = tid; i < F_; i += NTH) sk[i] = fkey(prow[i]);
    __syncthreads();
    select_topk(sk, hist, selIdx, eqIdx, K1, &sh);
    for (int j = tid; j < K1; j += NTH) {
        const int idx = selIdx[j];
        g_selIdx[(size_t)b * KSEL + j] = idx;
        g_selW[(size_t)b * KSEL + j]   = ikey(sk[idx]);   // bit-exact sp value
    }
    __syncthreads();   // all weight reads of sk done before overwrite

    // ---- pass 2: top-256 of fuzzed dead features (in-place key rebuild) ----
    const float* nrow = noise + (size_t)b * F_;
    for (int i = tid; i < F_; i += NTH) {
        const float v = ikey(sk[i]);                      // == sp[i] bits
        sk[i] = (last_usage[i] > DEAD_CUT) ? fkey(v + fuzz * nrow[i]) : 0u;
    }
    __syncthreads();
    select_topk(sk, hist, selIdx, eqIdx, K2_, &sh);
    for (int j = tid; j < K2_; j += NTH) {
        const int idx = selIdx[j];
        g_selIdx[(size_t)b * KSEL + K1 + j] = idx;
        g_selW[(size_t)b * KSEL + K1 + j]   = prow[idx];  // weight = project value
    }
}

// ---------------------------------------------------------------------------
// Reconstruction kernel: 2 CTAs per row, 512 threads, 1 d each.
// ---------------------------------------------------------------------------
__global__ __launch_bounds__(512)
void recon_kernel(const float* __restrict__ lookup,
                  const float* __restrict__ bias,
                  float* __restrict__ out)
{
    __shared__ int   sidx[KSEL];
    __shared__ float sw[KSEL];

    const int tid  = threadIdx.x;
    const int b    = blockIdx.x >> 1;
    const int half = blockIdx.x & 1;

    if (tid < KSEL) {
        sidx[tid] = g_selIdx[(size_t)b * KSEL + tid];
        sw[tid]   = g_selW[(size_t)b * KSEL + tid];
    }
    __syncthreads();

    const int d = half * 512 + tid;

    float a = bias[d];
#pragma unroll 8
    for (int k = 0; k < K1; k++)
        a += sw[k] * lookup[(size_t)sidx[k] * D_ + d];
    out[(size_t)b * D_ + d] = a;

    float a0 = 0.f, a1 = 0.f, a2 = 0.f, a3 = 0.f;
#pragma unroll 4
    for (int k = 0; k < K2_; k += 4) {
        a0 += sw[K1 + k + 0] * lookup[(size_t)sidx[K1 + k + 0] * D_ + d];
        a1 += sw[K1 + k + 1] * lookup[(size_t)sidx[K1 + k + 1] * D_ + d];
        a2 += sw[K1 + k + 2] * lookup[(size_t)sidx[K1 + k + 2] * D_ + d];
        a3 += sw[K1 + k + 3] * lookup[(size_t)sidx[K1 + k + 3] * D_ + d];
    }
    out[(size_t)B_ * D_ + (size_t)b * D_ + d] = (a0 + a1) + (a2 + a3);
}

// ---------------------------------------------------------------------------
// Launch
// ---------------------------------------------------------------------------
extern "C" void kernel_launch(void* const* d_in, const int* in_sizes, int n_in,
                              void* d_out, int out_size)
{
    (void)in_sizes; (void)n_in; (void)out_size;
    const float* embed      = (const float*)d_in[0];
    const float* enc_bias   = (const float*)d_in[1];
    const float* enc_W      = (const float*)d_in[2];
    const float* lookup     = (const float*)d_in[3];
    const float* noise      = (const float*)d_in[4];
    const int*   last_usage = (const int*)  d_in[5];
    float* out = (float*)d_out;

    // keys(96KB) + hist(8KB) + selIdx/eqIdx
    const size_t smem_bytes = (size_t)F_ * 4 + 2048 * 4 + 256 * 4 + 64 * 4; // 107776
    cudaFuncSetAttribute(select_kernel,
                         cudaFuncAttributeMaxDynamicSharedMemorySize,
                         (int)smem_bytes);

    gemm_kernel<<<dim3(GRID_X, GRID_Y), 512>>>(embed, enc_bias, enc_W);
    reduce_stats_kernel<<<1, 512>>>();
    select_kernel<<<B_, NTH, smem_bytes>>>(noise, last_usage);
    recon_kernel<<<B_ * 2, 512>>>(lookup, enc_bias, out);
}